// round 1
// baseline (speedup 1.0000x reference)
#include <cuda_runtime.h>
#include <math.h>

// Problem constants
#define Bb 8
#define TT 4096
#define HH 1024
#define SS 16
#define MM (Bb*TT)   // 32768 rows

// ---------------- scratch (device globals; no allocation allowed) -----------
__device__ float g_xp[MM*HH];   // projected input  (134 MB)
__device__ float g_y1[MM*HH];   // tanh(...) output (134 MB)
__device__ float g_z [MM*HH];   // pre-LN output    (134 MB)
__device__ float g_bx[MM*SS];
__device__ float g_ig[MM*SS];
__device__ float g_fg[MM*SS];
__device__ float g_hs[MM*SS];
__device__ float g_Wg[HH*48];   // [W_B@B_mat | W_ig | W_fg]
__device__ float g_bg[48];      // [b_B@B_mat | b_ig | b_fg]

// ---------------- precompute fused gate weights -----------------------------
__global__ void prep_kernel(const float* __restrict__ W_B, const float* __restrict__ b_B,
                            const float* __restrict__ B_mat,
                            const float* __restrict__ W_ig, const float* __restrict__ b_ig,
                            const float* __restrict__ W_fg, const float* __restrict__ b_fg)
{
    int tid = blockIdx.x * 256 + threadIdx.x;   // 0..16383
    int k = tid >> 4, s = tid & 15;
    float acc = 0.f;
    for (int h = 0; h < HH; h++)
        acc += W_B[k*HH + h] * B_mat[h*SS + s];
    g_Wg[k*48 + s]       = acc;
    g_Wg[k*48 + 16 + s]  = W_ig[k*SS + s];
    g_Wg[k*48 + 32 + s]  = W_fg[k*SS + s];
    if (tid < 48) {
        float bv;
        if (tid < 16) {
            float a = 0.f;
            for (int h = 0; h < HH; h++) a += b_B[h] * B_mat[h*SS + tid];
            bv = a;
        } else if (tid < 32) bv = b_ig[tid - 16];
        else                 bv = b_fg[tid - 32];
        g_bg[tid] = bv;
    }
}

// ---------------- 128x128x8 SIMT fp32 GEMM with fused epilogues --------------
// MODE 0: C = A@W + bias
// MODE 1: C = tanh(A@W + bias + hs@Cm)      (hs: [M,16], Cm: [16,N])
// MODE 2: C = A@W + bias + resid
template<int MODE>
__global__ void __launch_bounds__(256)
sgemm_kernel(const float* __restrict__ A, const float* __restrict__ W,
             const float* __restrict__ bias, float* __restrict__ C,
             const float* __restrict__ hs, const float* __restrict__ Cm,
             const float* __restrict__ resid, int M, int N, int K)
{
    __shared__ float As[8][132];
    __shared__ float Bs[8][128];

    const int t  = threadIdx.x;
    const int tx = t & 15, ty = t >> 4;
    const int m0 = blockIdx.y * 128, n0 = blockIdx.x * 128;

    float acc[8][8];
#pragma unroll
    for (int i = 0; i < 8; i++)
#pragma unroll
        for (int j = 0; j < 8; j++) acc[i][j] = 0.f;

    const int arow = t >> 1, acol = (t & 1) * 4;
    const int brow = t >> 5, bcol = (t & 31) * 4;

    for (int k0 = 0; k0 < K; k0 += 8) {
        float4 av = *(const float4*)&A[(size_t)(m0 + arow) * K + k0 + acol];
        float4 bv = *(const float4*)&W[(size_t)(k0 + brow) * N + n0 + bcol];
        As[acol+0][arow] = av.x; As[acol+1][arow] = av.y;
        As[acol+2][arow] = av.z; As[acol+3][arow] = av.w;
        *(float4*)&Bs[brow][bcol] = bv;
        __syncthreads();
#pragma unroll
        for (int k = 0; k < 8; k++) {
            float4 a0 = *(const float4*)&As[k][ty*4];
            float4 a1 = *(const float4*)&As[k][ty*4 + 64];
            float4 b0 = *(const float4*)&Bs[k][tx*4];
            float4 b1 = *(const float4*)&Bs[k][tx*4 + 64];
            float av8[8] = {a0.x, a0.y, a0.z, a0.w, a1.x, a1.y, a1.z, a1.w};
            float bv8[8] = {b0.x, b0.y, b0.z, b0.w, b1.x, b1.y, b1.z, b1.w};
#pragma unroll
            for (int i = 0; i < 8; i++)
#pragma unroll
                for (int j = 0; j < 8; j++)
                    acc[i][j] += av8[i] * bv8[j];
        }
        __syncthreads();
    }

    int rows[8], cols[8];
#pragma unroll
    for (int i = 0; i < 8; i++) {
        rows[i] = m0 + ty*4 + (i & 3) + ((i >> 2) * 64);
        cols[i] = n0 + tx*4 + (i & 3) + ((i >> 2) * 64);
    }

    float bi[8];
#pragma unroll
    for (int j = 0; j < 8; j++) bi[j] = bias[cols[j]];

    if (MODE == 1) {
        // add hs @ Cm (K=16)
#pragma unroll
        for (int s = 0; s < SS; s++) {
            float cv[8];
#pragma unroll
            for (int j = 0; j < 8; j++) cv[j] = Cm[s*N + cols[j]];
#pragma unroll
            for (int i = 0; i < 8; i++) {
                float hv = hs[rows[i]*SS + s];
#pragma unroll
                for (int j = 0; j < 8; j++) acc[i][j] += hv * cv[j];
            }
        }
    }

#pragma unroll
    for (int i = 0; i < 8; i++) {
#pragma unroll
        for (int j = 0; j < 8; j++) {
            float v = acc[i][j] + bi[j];
            if (MODE == 1) v = tanhf(v);
            if (MODE == 2) v += resid[(size_t)rows[i]*N + cols[j]];
            C[(size_t)rows[i]*N + cols[j]] = v;
        }
    }
}

// ---------------- fused 48-wide projection: Bx / ig / fg ---------------------
__global__ void __launch_bounds__(256)
proj48_kernel(const float* __restrict__ xp)
{
    __shared__ float xs[256][33];
    __shared__ float ws[32*48];
    const int t = threadIdx.x;
    const int m0 = blockIdx.x * 256;

    float acc[48];
#pragma unroll
    for (int c = 0; c < 48; c++) acc[c] = 0.f;

    for (int k0 = 0; k0 < HH; k0 += 32) {
#pragma unroll
        for (int i = 0; i < 8; i++) {
            int f = (t + 256*i) * 4;       // flat float index in 256x32 tile
            int r = f >> 5, c = f & 31;
            float4 v = *(const float4*)&xp[(size_t)(m0 + r) * HH + k0 + c];
            xs[r][c+0] = v.x; xs[r][c+1] = v.y; xs[r][c+2] = v.z; xs[r][c+3] = v.w;
        }
        for (int i = t; i < 384; i += 256)
            ((float4*)ws)[i] = ((const float4*)(g_Wg + k0*48))[i];
        __syncthreads();
#pragma unroll
        for (int k = 0; k < 32; k++) {
            float xv = xs[t][k];
#pragma unroll
            for (int c = 0; c < 48; c++) acc[c] += xv * ws[k*48 + c];
        }
        __syncthreads();
    }

    const int m = m0 + t;
#pragma unroll
    for (int s = 0; s < SS; s++) {
        g_bx[m*SS + s] = acc[s] + g_bg[s];
        g_ig[m*SS + s] = 1.f / (1.f + expf(-(acc[16 + s] + g_bg[16 + s])));
        g_fg[m*SS + s] = 1.f / (1.f + expf(-(acc[32 + s] + g_bg[32 + s])));
    }
}

// ---------------- sequential gated recurrence --------------------------------
__global__ void scan_kernel()
{
    const int tid = threadIdx.x;       // 0..127
    const int b = tid >> 4, s = tid & 15;
    float h = 0.f;
    const int base = b * TT * SS + s;
#pragma unroll 8
    for (int tt = 0; tt < TT; tt++) {
        int idx = base + tt * SS;
        h = g_fg[idx] * h + g_ig[idx] * g_bx[idx];
        g_hs[idx] = h;
    }
}

// ---------------- row LayerNorm ----------------------------------------------
__global__ void __launch_bounds__(256)
ln_kernel(const float* __restrict__ gamma, const float* __restrict__ beta,
          float* __restrict__ out)
{
    __shared__ float red0[8], red1[8];
    const int row = blockIdx.x, t = threadIdx.x;
    const float* p = g_z + (size_t)row * HH;

    float4 v = *(const float4*)&p[t*4];
    float s = v.x + v.y + v.z + v.w;
    float q = v.x*v.x + v.y*v.y + v.z*v.z + v.w*v.w;
#pragma unroll
    for (int o = 16; o; o >>= 1) {
        s += __shfl_xor_sync(0xffffffffu, s, o);
        q += __shfl_xor_sync(0xffffffffu, q, o);
    }
    if ((t & 31) == 0) { red0[t >> 5] = s; red1[t >> 5] = q; }
    __syncthreads();
    if (t == 0) {
        float ss = 0.f, qq = 0.f;
#pragma unroll
        for (int i = 0; i < 8; i++) { ss += red0[i]; qq += red1[i]; }
        red0[0] = ss; red1[0] = qq;
    }
    __syncthreads();
    float mu  = red0[0] * (1.f / HH);
    float var = red1[0] * (1.f / HH) - mu * mu;
    float rs  = rsqrtf(var + 1e-5f);

    float4 g4 = *(const float4*)&gamma[t*4];
    float4 b4 = *(const float4*)&beta[t*4];
    float4 o4;
    o4.x = (v.x - mu) * rs * g4.x + b4.x;
    o4.y = (v.y - mu) * rs * g4.y + b4.y;
    o4.z = (v.z - mu) * rs * g4.z + b4.z;
    o4.w = (v.w - mu) * rs * g4.w + b4.w;
    *(float4*)&out[(size_t)row * HH + t*4] = o4;
}

// ---------------- launch ------------------------------------------------------
extern "C" void kernel_launch(void* const* d_in, const int* in_sizes, int n_in,
                              void* d_out, int out_size)
{
    const float* x     = (const float*)d_in[0];
    const float* W_in  = (const float*)d_in[1];
    const float* b_in  = (const float*)d_in[2];
    const float* B_mat = (const float*)d_in[3];
    const float* C_mat = (const float*)d_in[4];
    const float* W_B   = (const float*)d_in[5];
    const float* b_B   = (const float*)d_in[6];
    const float* W_D   = (const float*)d_in[7];
    const float* b_D   = (const float*)d_in[8];
    const float* W_out = (const float*)d_in[9];
    const float* b_out = (const float*)d_in[10];
    const float* W_ig  = (const float*)d_in[11];
    const float* b_ig  = (const float*)d_in[12];
    const float* W_fg  = (const float*)d_in[13];
    const float* b_fg  = (const float*)d_in[14];
    const float* gamma = (const float*)d_in[15];
    const float* beta  = (const float*)d_in[16];
    float* out = (float*)d_out;

    void *p_xp, *p_y1, *p_z, *p_hs;
    cudaGetSymbolAddress(&p_xp, g_xp);
    cudaGetSymbolAddress(&p_y1, g_y1);
    cudaGetSymbolAddress(&p_z,  g_z);
    cudaGetSymbolAddress(&p_hs, g_hs);

    prep_kernel<<<64, 256>>>(W_B, b_B, B_mat, W_ig, b_ig, W_fg, b_fg);

    dim3 gg(HH/128, MM/128);   // (8, 256)

    // xp = x @ W_in + b_in
    sgemm_kernel<0><<<gg, 256>>>(x, W_in, b_in, (float*)p_xp,
                                 nullptr, nullptr, nullptr, MM, HH, HH);

    // Bx / ig / fg (fused 48-wide projection)
    proj48_kernel<<<MM/256, 256>>>((const float*)p_xp);

    // h_t = fg*h + ig*Bx
    scan_kernel<<<1, 128>>>();

    // y1 = tanh(xp @ W_D + b_D + hs @ C_mat)
    sgemm_kernel<1><<<gg, 256>>>((const float*)p_xp, W_D, b_D, (float*)p_y1,
                                 (const float*)p_hs, C_mat, nullptr, MM, HH, HH);

    // z = y1 @ W_out + b_out + xp
    sgemm_kernel<2><<<gg, 256>>>((const float*)p_y1, W_out, b_out, (float*)p_z,
                                 nullptr, nullptr, (const float*)p_xp, MM, HH, HH);

    // out = LayerNorm(z)
    ln_kernel<<<MM, 256>>>(gamma, beta, out);
}

// round 4
// speedup vs baseline: 1.1339x; 1.1339x over previous
#include <cuda_runtime.h>
#include <math.h>
#include <stdint.h>

// Problem constants
#define Bb 8
#define TT 4096
#define HH 1024
#define SS 16
#define MM (Bb*TT)   // 32768 rows

// ---------------- scratch (device globals; no allocation allowed) -----------
__device__ float g_xp[MM*HH];   // projected input  (134 MB)
__device__ float g_y1[MM*HH];   // tanh(...) output (134 MB)
__device__ float g_z [MM*HH];   // pre-LN output    (134 MB)
__device__ float g_bx[MM*SS];
__device__ float g_ig[MM*SS];
__device__ float g_fg[MM*SS];
__device__ float g_hs[MM*SS];
__device__ float g_Wg[HH*48];   // [W_B@B_mat | W_ig | W_fg]
__device__ float g_bg[48];      // [b_B@B_mat | b_ig | b_fg]

// ---------------- small helpers ---------------------------------------------
__device__ __forceinline__ uint32_t f2tf(float x) {
    uint32_t u;
    asm("cvt.rna.tf32.f32 %0, %1;" : "=r"(u) : "f"(x));
    return u;
}
__device__ __forceinline__ void split_tf32(float x, uint32_t& hi, uint32_t& lo) {
    hi = f2tf(x);
    lo = f2tf(x - __uint_as_float(hi));
}
__device__ __forceinline__ void mma8(float* c, const uint32_t* a, const uint32_t* b) {
    asm volatile(
        "mma.sync.aligned.m16n8k8.row.col.f32.tf32.tf32.f32 "
        "{%0,%1,%2,%3}, {%4,%5,%6,%7}, {%8,%9}, {%0,%1,%2,%3};\n"
        : "+f"(c[0]), "+f"(c[1]), "+f"(c[2]), "+f"(c[3])
        : "r"(a[0]), "r"(a[1]), "r"(a[2]), "r"(a[3]), "r"(b[0]), "r"(b[1]));
}
__device__ __forceinline__ void cp16(void* smem, const void* g) {
    uint32_t s = (uint32_t)__cvta_generic_to_shared(smem);
    asm volatile("cp.async.ca.shared.global [%0], [%1], 16;\n" :: "r"(s), "l"(g));
}
__device__ __forceinline__ void cp_commit() {
    asm volatile("cp.async.commit_group;\n" ::: "memory");
}
template<int N>
__device__ __forceinline__ void cp_wait() {
    asm volatile("cp.async.wait_group %0;\n" :: "n"(N) : "memory");
}

// ---------------- precompute fused gate weights -----------------------------
__global__ void prep_kernel(const float* __restrict__ W_B, const float* __restrict__ b_B,
                            const float* __restrict__ B_mat,
                            const float* __restrict__ W_ig, const float* __restrict__ b_ig,
                            const float* __restrict__ W_fg, const float* __restrict__ b_fg)
{
    int tid = blockIdx.x * 256 + threadIdx.x;   // 0..16383
    int k = tid >> 4, s = tid & 15;
    float acc = 0.f;
    for (int h = 0; h < HH; h++)
        acc += W_B[k*HH + h] * B_mat[h*SS + s];
    g_Wg[k*48 + s]       = acc;
    g_Wg[k*48 + 16 + s]  = W_ig[k*SS + s];
    g_Wg[k*48 + 32 + s]  = W_fg[k*SS + s];
    if (tid < 16) {
        float a = 0.f;
        for (int h = 0; h < HH; h++) a += b_B[h] * B_mat[h*SS + tid];
        g_bg[tid] = a;
    } else if (tid < 32) {
        g_bg[tid] = b_ig[tid - 16];
    } else if (tid < 48) {
        g_bg[tid] = b_fg[tid - 32];
    }
}

// ---------------- 128x128x16 tf32 tensor-core GEMM (3xTF32) -----------------
// MODE 0: C = A@W + bias
// MODE 1: C = tanh(A@W + bias + hs@Cm)      (hs: [M,16], Cm: [16,N])
// MODE 2: C = A@W + bias + resid
#define NITER (HH/16)   // 64
template<int MODE>
__global__ void __launch_bounds__(256)
tgemm_kernel(const float* __restrict__ A, const float* __restrict__ W,
             const float* __restrict__ bias, float* __restrict__ C,
             const float* __restrict__ hs, const float* __restrict__ Cm,
             const float* __restrict__ resid, int M, int N, int K)
{
    __shared__ float As[2][128][20];   // [buf][m][k], stride 20 floats (16B aligned)
    __shared__ float Ws[2][16][132];   // [buf][k][n], stride 132 floats (16B aligned)

    const int t    = threadIdx.x;
    const int warp = t >> 5, lane = t & 31;
    const int gid  = lane >> 2, tg = lane & 3;
    const int wm   = warp & 1;          // warp grid: 2 (m) x 4 (n)
    const int wn   = warp >> 1;
    const int m0 = blockIdx.y * 128, n0 = blockIdx.x * 128;

    float acc[4][4][4];
#pragma unroll
    for (int i = 0; i < 4; i++)
#pragma unroll
        for (int j = 0; j < 4; j++)
#pragma unroll
            for (int e = 0; e < 4; e++) acc[i][j][e] = 0.f;

    // tile loader: A[128x16], W[16x128] at k-offset k0 -> buffer buf
    auto loadTiles = [&](int k0, int buf) {
#pragma unroll
        for (int i = 0; i < 2; i++) {
            int id = t + i * 256;                 // 0..511
            int r = id >> 2, c = (id & 3) * 4;
            cp16(&As[buf][r][c], &A[(size_t)(m0 + r) * K + k0 + c]);
        }
#pragma unroll
        for (int i = 0; i < 2; i++) {
            int id = t + i * 256;
            int r = id >> 5, c = (id & 31) * 4;
            cp16(&Ws[buf][r][c], &W[(size_t)(k0 + r) * N + n0 + c]);
        }
    };

    loadTiles(0, 0);
    cp_commit();

    for (int it = 0; it < NITER; it++) {
        const int buf = it & 1;
        if (it < NITER - 1) {
            loadTiles((it + 1) * 16, buf ^ 1);
            cp_commit();
            cp_wait<1>();
        } else {
            cp_wait<0>();
        }
        __syncthreads();

#pragma unroll
        for (int kk = 0; kk < 16; kk += 8) {
            // B (weight) fragments first: reused by all 4 i-iterations
            uint32_t bhi[4][2], blo[4][2];
#pragma unroll
            for (int j = 0; j < 4; j++) {
                int n = wn * 32 + j * 8 + gid;
                split_tf32(Ws[buf][kk + tg    ][n], bhi[j][0], blo[j][0]);
                split_tf32(Ws[buf][kk + tg + 4][n], bhi[j][1], blo[j][1]);
            }
            uint32_t ahi[4][4], alo[4][4];
#pragma unroll
            for (int i = 0; i < 4; i++) {
                int r = wm * 64 + i * 16 + gid;
                split_tf32(As[buf][r    ][kk + tg    ], ahi[i][0], alo[i][0]);
                split_tf32(As[buf][r + 8][kk + tg    ], ahi[i][1], alo[i][1]);
                split_tf32(As[buf][r    ][kk + tg + 4], ahi[i][2], alo[i][2]);
                split_tf32(As[buf][r + 8][kk + tg + 4], ahi[i][3], alo[i][3]);
            }
#pragma unroll
            for (int i = 0; i < 4; i++)
#pragma unroll
                for (int j = 0; j < 4; j++) {
                    mma8(acc[i][j], ahi[i], bhi[j]);
                    mma8(acc[i][j], ahi[i], blo[j]);
                    mma8(acc[i][j], alo[i], bhi[j]);
                }
        }
        __syncthreads();
    }

    // ---------------- epilogue ----------------
#pragma unroll
    for (int i = 0; i < 4; i++) {
        int r0 = m0 + wm * 64 + i * 16 + gid;   // rows r0, r0+8
        float h0[SS], h1[SS];
        if (MODE == 1) {
#pragma unroll
            for (int s4 = 0; s4 < SS; s4 += 4) {
                float4 a = *(const float4*)&hs[(size_t)r0 * SS + s4];
                float4 b = *(const float4*)&hs[(size_t)(r0 + 8) * SS + s4];
                h0[s4] = a.x; h0[s4+1] = a.y; h0[s4+2] = a.z; h0[s4+3] = a.w;
                h1[s4] = b.x; h1[s4+1] = b.y; h1[s4+2] = b.z; h1[s4+3] = b.w;
            }
        }
#pragma unroll
        for (int j = 0; j < 4; j++) {
            int c0 = n0 + wn * 32 + j * 8 + tg * 2;  // cols c0, c0+1
            float v[4] = {acc[i][j][0], acc[i][j][1], acc[i][j][2], acc[i][j][3]};
            float bi0 = __ldg(&bias[c0]), bi1 = __ldg(&bias[c0 + 1]);
            v[0] += bi0; v[1] += bi1; v[2] += bi0; v[3] += bi1;
            if (MODE == 1) {
#pragma unroll
                for (int s = 0; s < SS; s++) {
                    float cm0 = __ldg(&Cm[s * N + c0]);
                    float cm1 = __ldg(&Cm[s * N + c0 + 1]);
                    v[0] += h0[s] * cm0; v[1] += h0[s] * cm1;
                    v[2] += h1[s] * cm0; v[3] += h1[s] * cm1;
                }
                v[0] = tanhf(v[0]); v[1] = tanhf(v[1]);
                v[2] = tanhf(v[2]); v[3] = tanhf(v[3]);
            }
            if (MODE == 2) {
                v[0] += resid[(size_t)r0 * N + c0];
                v[1] += resid[(size_t)r0 * N + c0 + 1];
                v[2] += resid[(size_t)(r0 + 8) * N + c0];
                v[3] += resid[(size_t)(r0 + 8) * N + c0 + 1];
            }
            C[(size_t)r0 * N + c0]           = v[0];
            C[(size_t)r0 * N + c0 + 1]       = v[1];
            C[(size_t)(r0 + 8) * N + c0]     = v[2];
            C[(size_t)(r0 + 8) * N + c0 + 1] = v[3];
        }
    }
}

// ---------------- fused 48-wide projection: Bx / ig / fg ---------------------
__global__ void __launch_bounds__(256)
proj48_kernel(const float* __restrict__ xp)
{
    __shared__ float xs[256][33];
    __shared__ float ws[32*48];
    const int t = threadIdx.x;
    const int m0 = blockIdx.x * 256;

    float acc[48];
#pragma unroll
    for (int c = 0; c < 48; c++) acc[c] = 0.f;

    for (int k0 = 0; k0 < HH; k0 += 32) {
#pragma unroll
        for (int i = 0; i < 8; i++) {
            int f = (t + 256*i) * 4;       // flat float index in 256x32 tile
            int r = f >> 5, c = f & 31;
            float4 v = *(const float4*)&xp[(size_t)(m0 + r) * HH + k0 + c];
            xs[r][c+0] = v.x; xs[r][c+1] = v.y; xs[r][c+2] = v.z; xs[r][c+3] = v.w;
        }
        for (int i = t; i < 384; i += 256)
            ((float4*)ws)[i] = ((const float4*)(g_Wg + k0*48))[i];
        __syncthreads();
#pragma unroll
        for (int k = 0; k < 32; k++) {
            float xv = xs[t][k];
#pragma unroll
            for (int c = 0; c < 48; c++) acc[c] += xv * ws[k*48 + c];
        }
        __syncthreads();
    }

    const int m = m0 + t;
#pragma unroll
    for (int s = 0; s < SS; s++) {
        g_bx[m*SS + s] = acc[s] + g_bg[s];
        g_ig[m*SS + s] = 1.f / (1.f + expf(-(acc[16 + s] + g_bg[16 + s])));
        g_fg[m*SS + s] = 1.f / (1.f + expf(-(acc[32 + s] + g_bg[32 + s])));
    }
}

// ---------------- sequential gated recurrence --------------------------------
__global__ void scan_kernel()
{
    const int tid = threadIdx.x;       // 0..127
    const int b = tid >> 4, s = tid & 15;
    float h = 0.f;
    const int base = b * TT * SS + s;
#pragma unroll 8
    for (int tt = 0; tt < TT; tt++) {
        int idx = base + tt * SS;
        h = g_fg[idx] * h + g_ig[idx] * g_bx[idx];
        g_hs[idx] = h;
    }
}

// ---------------- row LayerNorm ----------------------------------------------
__global__ void __launch_bounds__(256)
ln_kernel(const float* __restrict__ gamma, const float* __restrict__ beta,
          float* __restrict__ out)
{
    __shared__ float red0[8], red1[8];
    const int row = blockIdx.x, t = threadIdx.x;
    const float* p = g_z + (size_t)row * HH;

    float4 v = *(const float4*)&p[t*4];
    float s = v.x + v.y + v.z + v.w;
    float q = v.x*v.x + v.y*v.y + v.z*v.z + v.w*v.w;
#pragma unroll
    for (int o = 16; o; o >>= 1) {
        s += __shfl_xor_sync(0xffffffffu, s, o);
        q += __shfl_xor_sync(0xffffffffu, q, o);
    }
    if ((t & 31) == 0) { red0[t >> 5] = s; red1[t >> 5] = q; }
    __syncthreads();
    if (t == 0) {
        float ss = 0.f, qq = 0.f;
#pragma unroll
        for (int i = 0; i < 8; i++) { ss += red0[i]; qq += red1[i]; }
        red0[0] = ss; red1[0] = qq;
    }
    __syncthreads();
    float mu  = red0[0] * (1.f / HH);
    float var = red1[0] * (1.f / HH) - mu * mu;
    float rs  = rsqrtf(var + 1e-5f);

    float4 g4 = *(const float4*)&gamma[t*4];
    float4 b4 = *(const float4*)&beta[t*4];
    float4 o4;
    o4.x = (v.x - mu) * rs * g4.x + b4.x;
    o4.y = (v.y - mu) * rs * g4.y + b4.y;
    o4.z = (v.z - mu) * rs * g4.z + b4.z;
    o4.w = (v.w - mu) * rs * g4.w + b4.w;
    *(float4*)&out[(size_t)row * HH + t*4] = o4;
}

// ---------------- launch ------------------------------------------------------
extern "C" void kernel_launch(void* const* d_in, const int* in_sizes, int n_in,
                              void* d_out, int out_size)
{
    const float* x     = (const float*)d_in[0];
    const float* W_in  = (const float*)d_in[1];
    const float* b_in  = (const float*)d_in[2];
    const float* B_mat = (const float*)d_in[3];
    const float* C_mat = (const float*)d_in[4];
    const float* W_B   = (const float*)d_in[5];
    const float* b_B   = (const float*)d_in[6];
    const float* W_D   = (const float*)d_in[7];
    const float* b_D   = (const float*)d_in[8];
    const float* W_out = (const float*)d_in[9];
    const float* b_out = (const float*)d_in[10];
    const float* W_ig  = (const float*)d_in[11];
    const float* b_ig  = (const float*)d_in[12];
    const float* W_fg  = (const float*)d_in[13];
    const float* b_fg  = (const float*)d_in[14];
    const float* gamma = (const float*)d_in[15];
    const float* beta  = (const float*)d_in[16];
    float* out = (float*)d_out;

    void *p_xp, *p_y1, *p_z, *p_hs;
    cudaGetSymbolAddress(&p_xp, g_xp);
    cudaGetSymbolAddress(&p_y1, g_y1);
    cudaGetSymbolAddress(&p_z,  g_z);
    cudaGetSymbolAddress(&p_hs, g_hs);

    prep_kernel<<<64, 256>>>(W_B, b_B, B_mat, W_ig, b_ig, W_fg, b_fg);

    dim3 gg(HH/128, MM/128);   // (8, 256)

    // xp = x @ W_in + b_in
    tgemm_kernel<0><<<gg, 256>>>(x, W_in, b_in, (float*)p_xp,
                                 nullptr, nullptr, nullptr, MM, HH, HH);

    // Bx / ig / fg (fused 48-wide projection)
    proj48_kernel<<<MM/256, 256>>>((const float*)p_xp);

    // h_t = fg*h + ig*Bx
    scan_kernel<<<1, 128>>>();

    // y1 = tanh(xp @ W_D + b_D + hs @ C_mat)
    tgemm_kernel<1><<<gg, 256>>>((const float*)p_xp, W_D, b_D, (float*)p_y1,
                                 (const float*)p_hs, C_mat, nullptr, MM, HH, HH);

    // z = y1 @ W_out + b_out + xp
    tgemm_kernel<2><<<gg, 256>>>((const float*)p_y1, W_out, b_out, (float*)p_z,
                                 nullptr, nullptr, (const float*)p_xp, MM, HH, HH);

    // out = LayerNorm(z)
    ln_kernel<<<MM, 256>>>(gamma, beta, out);
}

// round 5
// speedup vs baseline: 1.7068x; 1.5052x over previous
#include <cuda_runtime.h>
#include <cuda_bf16.h>
#include <math.h>
#include <stdint.h>

// Problem constants
#define Bb 8
#define TT 4096
#define HH 1024
#define SS 16
#define MM (Bb*TT)   // 32768 rows

// ---------------- scratch (device globals; no allocation allowed) -----------
__device__ float g_xp[MM*HH];    // projected input fp32 (proj48 + residual)
__device__ float g_z [MM*HH];    // pre-LN output
__device__ float g_bx[MM*SS];
__device__ float g_ig[MM*SS];
__device__ float g_fg[MM*SS];
__device__ float g_hs[MM*SS];
__device__ float g_Wg[HH*48];    // [W_B@B_mat | W_ig | W_fg]
__device__ float g_bg[48];       // [b_B@B_mat | b_ig | b_fg]
// bf16 hi/lo packed pairs (2 bf16 per uint32)
__device__ uint32_t g_xhi [MM*HH/2], g_xlo [MM*HH/2];
__device__ uint32_t g_xphi[MM*HH/2], g_xplo[MM*HH/2];
__device__ uint32_t g_y1hi[MM*HH/2], g_y1lo[MM*HH/2];
__device__ uint32_t g_w0hi[HH*HH/2], g_w0lo[HH*HH/2];
__device__ uint32_t g_w1hi[HH*HH/2], g_w1lo[HH*HH/2];
__device__ uint32_t g_w2hi[HH*HH/2], g_w2lo[HH*HH/2];

// ---------------- helpers ----------------------------------------------------
__device__ __forceinline__ void bsplit(float v, uint16_t& h, uint16_t& l) {
    __nv_bfloat16 hb = __float2bfloat16(v);
    float hf = __bfloat162float(hb);
    __nv_bfloat16 lb = __float2bfloat16(v - hf);
    h = __bfloat16_as_ushort(hb);
    l = __bfloat16_as_ushort(lb);
}
__device__ __forceinline__ uint32_t pack2(uint16_t a, uint16_t b) {
    return (uint32_t)a | ((uint32_t)b << 16);
}
__device__ __forceinline__ void ldm_x4(uint32_t* r, uint32_t addr) {
    asm volatile("ldmatrix.sync.aligned.m8n8.x4.shared.b16 {%0,%1,%2,%3}, [%4];"
        : "=r"(r[0]), "=r"(r[1]), "=r"(r[2]), "=r"(r[3]) : "r"(addr));
}
__device__ __forceinline__ void ldm_x4_t(uint32_t* r, uint32_t addr) {
    asm volatile("ldmatrix.sync.aligned.m8n8.x4.trans.shared.b16 {%0,%1,%2,%3}, [%4];"
        : "=r"(r[0]), "=r"(r[1]), "=r"(r[2]), "=r"(r[3]) : "r"(addr));
}
__device__ __forceinline__ void mma16(float* c, const uint32_t* a, uint32_t b0, uint32_t b1) {
    asm volatile(
        "mma.sync.aligned.m16n8k16.row.col.f32.bf16.bf16.f32 "
        "{%0,%1,%2,%3}, {%4,%5,%6,%7}, {%8,%9}, {%0,%1,%2,%3};\n"
        : "+f"(c[0]), "+f"(c[1]), "+f"(c[2]), "+f"(c[3])
        : "r"(a[0]), "r"(a[1]), "r"(a[2]), "r"(a[3]), "r"(b0), "r"(b1));
}
__device__ __forceinline__ void cp16(uint32_t saddr, const void* g) {
    asm volatile("cp.async.ca.shared.global [%0], [%1], 16;\n" :: "r"(saddr), "l"(g));
}
__device__ __forceinline__ void cp_commit() {
    asm volatile("cp.async.commit_group;\n" ::: "memory");
}
template<int N>
__device__ __forceinline__ void cp_wait() {
    asm volatile("cp.async.wait_group %0;\n" :: "n"(N) : "memory");
}

// ---------------- bf16 hi/lo splitter (pairs) --------------------------------
__global__ void __launch_bounds__(256)
split_kernel(const float* __restrict__ src, uint32_t* __restrict__ dhi,
             uint32_t* __restrict__ dlo, int n2)
{
    int i = blockIdx.x * 256 + threadIdx.x;
    if (i >= n2) return;
    float2 v = ((const float2*)src)[i];
    uint16_t h0, l0, h1, l1;
    bsplit(v.x, h0, l0);
    bsplit(v.y, h1, l1);
    dhi[i] = pack2(h0, h1);
    dlo[i] = pack2(l0, l1);
}

// ---------------- precompute fused gate weights ------------------------------
__global__ void prep_kernel(const float* __restrict__ W_B, const float* __restrict__ b_B,
                            const float* __restrict__ B_mat,
                            const float* __restrict__ W_ig, const float* __restrict__ b_ig,
                            const float* __restrict__ W_fg, const float* __restrict__ b_fg)
{
    int tid = blockIdx.x * 256 + threadIdx.x;   // 0..16383
    int k = tid >> 4, s = tid & 15;
    float acc = 0.f;
    for (int h = 0; h < HH; h++)
        acc += W_B[k*HH + h] * B_mat[h*SS + s];
    g_Wg[k*48 + s]       = acc;
    g_Wg[k*48 + 16 + s]  = W_ig[k*SS + s];
    g_Wg[k*48 + 32 + s]  = W_fg[k*SS + s];
    if (tid < 16) {
        float a = 0.f;
        for (int h = 0; h < HH; h++) a += b_B[h] * B_mat[h*SS + tid];
        g_bg[tid] = a;
    } else if (tid < 32) {
        g_bg[tid] = b_ig[tid - 16];
    } else if (tid < 48) {
        g_bg[tid] = b_fg[tid - 32];
    }
}

// ---------------- 128x128x32 bf16 tensor-core GEMM (3-term emulation) --------
// A given as hi/lo bf16 [M,K]; W as hi/lo bf16 [K,N].
// MODE 0: xp = A@W + bias         -> C fp32 + Chi/Clo
// MODE 1: y1 = tanh(A@W + bias + hs@Cm) -> Chi/Clo only
// MODE 2: z  = A@W + bias + resid -> C fp32 only
#define BK 32
#define NITER (HH/BK)   // 32
// smem layout (uint16 units): A[buf][half]: 128 rows x stride 40
//                             W[buf][half]: 32 rows x stride 136
#define A_HALF  (128*40)                 // 5120
#define A_BUF   (2*A_HALF)               // 10240
#define W_BASE  (2*A_BUF)                // 20480
#define W_HALF  (32*136)                 // 4352
#define W_BUF   (2*W_HALF)               // 8704
#define SMEM_U16 (W_BASE + 2*W_BUF)      // 37888
#define SMEM_BYTES (SMEM_U16*2)          // 75776

template<int MODE>
__global__ void __launch_bounds__(256)
bgemm_kernel(const uint16_t* __restrict__ Ahi, const uint16_t* __restrict__ Alo,
             const uint16_t* __restrict__ Whi, const uint16_t* __restrict__ Wlo,
             const float* __restrict__ bias, float* __restrict__ C,
             uint32_t* __restrict__ Chi, uint32_t* __restrict__ Clo,
             const float* __restrict__ hs, const float* __restrict__ Cm,
             const float* __restrict__ resid, int M, int N, int K)
{
    extern __shared__ uint16_t sm[];
    const uint32_t smbase = (uint32_t)__cvta_generic_to_shared(sm);

    const int t    = threadIdx.x;
    const int warp = t >> 5, lane = t & 31;
    const int gid  = lane >> 2, tg = lane & 3;
    const int wm   = warp & 1;          // warp grid: 2 (m) x 4 (n); warp tile 64x32
    const int wn   = warp >> 1;
    const int m0 = blockIdx.y * 128, n0 = blockIdx.x * 128;

    float acc[4][4][4];
#pragma unroll
    for (int i = 0; i < 4; i++)
#pragma unroll
        for (int j = 0; j < 4; j++)
#pragma unroll
            for (int e = 0; e < 4; e++) acc[i][j][e] = 0.f;

    // tile loader: A[128xBK] hi+lo, W[BKx128] hi+lo -> buffer buf
    auto loadTiles = [&](int k0, int buf) {
#pragma unroll
        for (int h = 0; h < 2; h++) {
            const uint16_t* Ap = h ? Alo : Ahi;
            uint32_t abase = smbase + 2*(buf*A_BUF + h*A_HALF);
#pragma unroll
            for (int ci = 0; ci < 2; ci++) {
                int c = t + 256*ci;            // 0..511
                int row = c >> 2, off = (c & 3) * 8;
                cp16(abase + 2*(row*40 + off),
                     &Ap[(size_t)(m0 + row) * K + k0 + off]);
            }
        }
#pragma unroll
        for (int h = 0; h < 2; h++) {
            const uint16_t* Wp = h ? Wlo : Whi;
            uint32_t wbase = smbase + 2*(W_BASE + buf*W_BUF + h*W_HALF);
#pragma unroll
            for (int ci = 0; ci < 2; ci++) {
                int c = t + 256*ci;            // 0..511
                int row = c >> 4, off = (c & 15) * 8;
                cp16(wbase + 2*(row*136 + off),
                     &Wp[(size_t)(k0 + row) * N + n0 + off]);
            }
        }
    };

    loadTiles(0, 0);
    cp_commit();

    const int alane_r = lane & 15;       // row within 16 (A) / k within 16 (B)
    const int alane_c = (lane >> 4) * 8; // k-offset 0/8 (A) / n-offset 0/8 (B)

    for (int it = 0; it < NITER; it++) {
        const int buf = it & 1;
        if (it < NITER - 1) {
            loadTiles((it + 1) * BK, buf ^ 1);
            cp_commit();
            cp_wait<1>();
        } else {
            cp_wait<0>();
        }
        __syncthreads();

#pragma unroll
        for (int kk = 0; kk < BK; kk += 16) {
            // A fragments (hi & lo): 4 m16 tiles
            uint32_t ah[4][4], al[4][4];
#pragma unroll
            for (int i = 0; i < 4; i++) {
                int r = wm*64 + i*16 + alane_r;
                uint32_t off = 2u*(buf*A_BUF + r*40 + kk + alane_c);
                ldm_x4(ah[i], smbase + off);
                ldm_x4(al[i], smbase + off + 2u*A_HALF);
            }
            // B fragments (hi & lo): 2 n16 groups (trans from [k][n])
            uint32_t bh[2][4], bl[2][4];
#pragma unroll
            for (int g = 0; g < 2; g++) {
                int r = kk + alane_r;
                int cc = wn*32 + g*16 + alane_c;
                uint32_t off = 2u*(W_BASE + buf*W_BUF + r*136 + cc);
                ldm_x4_t(bh[g], smbase + off);
                ldm_x4_t(bl[g], smbase + off + 2u*W_HALF);
            }
#pragma unroll
            for (int i = 0; i < 4; i++)
#pragma unroll
                for (int j = 0; j < 4; j++) {
                    int g = j >> 1, p = j & 1;
                    mma16(acc[i][j], ah[i], bh[g][p*2], bh[g][p*2+1]);
                    mma16(acc[i][j], ah[i], bl[g][p*2], bl[g][p*2+1]);
                    mma16(acc[i][j], al[i], bh[g][p*2], bh[g][p*2+1]);
                }
        }
        __syncthreads();
    }

    // ---------------- epilogue ----------------
#pragma unroll
    for (int i = 0; i < 4; i++) {
        int r0 = m0 + wm * 64 + i * 16 + gid;   // rows r0, r0+8
        float h0[SS], h1[SS];
        if (MODE == 1) {
#pragma unroll
            for (int s4 = 0; s4 < SS; s4 += 4) {
                float4 a = *(const float4*)&hs[(size_t)r0 * SS + s4];
                float4 b = *(const float4*)&hs[(size_t)(r0 + 8) * SS + s4];
                h0[s4] = a.x; h0[s4+1] = a.y; h0[s4+2] = a.z; h0[s4+3] = a.w;
                h1[s4] = b.x; h1[s4+1] = b.y; h1[s4+2] = b.z; h1[s4+3] = b.w;
            }
        }
#pragma unroll
        for (int j = 0; j < 4; j++) {
            int c0 = n0 + wn * 32 + j * 8 + tg * 2;  // cols c0, c0+1 (c0 even)
            float v[4] = {acc[i][j][0], acc[i][j][1], acc[i][j][2], acc[i][j][3]};
            float bi0 = __ldg(&bias[c0]), bi1 = __ldg(&bias[c0 + 1]);
            v[0] += bi0; v[1] += bi1; v[2] += bi0; v[3] += bi1;
            if (MODE == 1) {
#pragma unroll
                for (int s = 0; s < SS; s++) {
                    float cm0 = __ldg(&Cm[s * N + c0]);
                    float cm1 = __ldg(&Cm[s * N + c0 + 1]);
                    v[0] += h0[s] * cm0; v[1] += h0[s] * cm1;
                    v[2] += h1[s] * cm0; v[3] += h1[s] * cm1;
                }
                v[0] = tanhf(v[0]); v[1] = tanhf(v[1]);
                v[2] = tanhf(v[2]); v[3] = tanhf(v[3]);
            }
            if (MODE == 2) {
                v[0] += resid[(size_t)r0 * N + c0];
                v[1] += resid[(size_t)r0 * N + c0 + 1];
                v[2] += resid[(size_t)(r0 + 8) * N + c0];
                v[3] += resid[(size_t)(r0 + 8) * N + c0 + 1];
            }
            if (MODE == 0 || MODE == 2) {
                C[(size_t)r0 * N + c0]           = v[0];
                C[(size_t)r0 * N + c0 + 1]       = v[1];
                C[(size_t)(r0 + 8) * N + c0]     = v[2];
                C[(size_t)(r0 + 8) * N + c0 + 1] = v[3];
            }
            if (MODE == 0 || MODE == 1) {
                uint16_t hh0, ll0, hh1, ll1;
                size_t p0 = ((size_t)r0 * N + c0) >> 1;
                size_t p1 = ((size_t)(r0 + 8) * N + c0) >> 1;
                bsplit(v[0], hh0, ll0); bsplit(v[1], hh1, ll1);
                Chi[p0] = pack2(hh0, hh1); Clo[p0] = pack2(ll0, ll1);
                bsplit(v[2], hh0, ll0); bsplit(v[3], hh1, ll1);
                Chi[p1] = pack2(hh0, hh1); Clo[p1] = pack2(ll0, ll1);
            }
        }
    }
}

// ---------------- fused 48-wide projection: Bx / ig / fg ---------------------
__global__ void __launch_bounds__(256)
proj48_kernel(const float* __restrict__ xp)
{
    __shared__ float xs[256][33];
    __shared__ float ws[32*48];
    const int t = threadIdx.x;
    const int m0 = blockIdx.x * 256;

    float acc[48];
#pragma unroll
    for (int c = 0; c < 48; c++) acc[c] = 0.f;

    for (int k0 = 0; k0 < HH; k0 += 32) {
#pragma unroll
        for (int i = 0; i < 8; i++) {
            int f = (t + 256*i) * 4;       // flat float index in 256x32 tile
            int r = f >> 5, c = f & 31;
            float4 v = *(const float4*)&xp[(size_t)(m0 + r) * HH + k0 + c];
            xs[r][c+0] = v.x; xs[r][c+1] = v.y; xs[r][c+2] = v.z; xs[r][c+3] = v.w;
        }
        for (int i = t; i < 384; i += 256)
            ((float4*)ws)[i] = ((const float4*)(g_Wg + k0*48))[i];
        __syncthreads();
#pragma unroll
        for (int k = 0; k < 32; k++) {
            float xv = xs[t][k];
#pragma unroll
            for (int c = 0; c < 48; c++) acc[c] += xv * ws[k*48 + c];
        }
        __syncthreads();
    }

    const int m = m0 + t;
#pragma unroll
    for (int s = 0; s < SS; s++) {
        g_bx[m*SS + s] = acc[s] + g_bg[s];
        g_ig[m*SS + s] = 1.f / (1.f + expf(-(acc[16 + s] + g_bg[16 + s])));
        g_fg[m*SS + s] = 1.f / (1.f + expf(-(acc[32 + s] + g_bg[32 + s])));
    }
}

// ---------------- sequential gated recurrence --------------------------------
__global__ void scan_kernel()
{
    const int tid = threadIdx.x;       // 0..127
    const int b = tid >> 4, s = tid & 15;
    float h = 0.f;
    const int base = b * TT * SS + s;
#pragma unroll 8
    for (int tt = 0; tt < TT; tt++) {
        int idx = base + tt * SS;
        h = g_fg[idx] * h + g_ig[idx] * g_bx[idx];
        g_hs[idx] = h;
    }
}

// ---------------- row LayerNorm ----------------------------------------------
__global__ void __launch_bounds__(256)
ln_kernel(const float* __restrict__ gamma, const float* __restrict__ beta,
          float* __restrict__ out)
{
    __shared__ float red0[8], red1[8];
    const int row = blockIdx.x, t = threadIdx.x;
    const float* p = g_z + (size_t)row * HH;

    float4 v = *(const float4*)&p[t*4];
    float s = v.x + v.y + v.z + v.w;
    float q = v.x*v.x + v.y*v.y + v.z*v.z + v.w*v.w;
#pragma unroll
    for (int o = 16; o; o >>= 1) {
        s += __shfl_xor_sync(0xffffffffu, s, o);
        q += __shfl_xor_sync(0xffffffffu, q, o);
    }
    if ((t & 31) == 0) { red0[t >> 5] = s; red1[t >> 5] = q; }
    __syncthreads();
    if (t == 0) {
        float ss = 0.f, qq = 0.f;
#pragma unroll
        for (int i = 0; i < 8; i++) { ss += red0[i]; qq += red1[i]; }
        red0[0] = ss; red1[0] = qq;
    }
    __syncthreads();
    float mu  = red0[0] * (1.f / HH);
    float var = red1[0] * (1.f / HH) - mu * mu;
    float rs  = rsqrtf(var + 1e-5f);

    float4 g4 = *(const float4*)&gamma[t*4];
    float4 b4 = *(const float4*)&beta[t*4];
    float4 o4;
    o4.x = (v.x - mu) * rs * g4.x + b4.x;
    o4.y = (v.y - mu) * rs * g4.y + b4.y;
    o4.z = (v.z - mu) * rs * g4.z + b4.z;
    o4.w = (v.w - mu) * rs * g4.w + b4.w;
    *(float4*)&out[(size_t)row * HH + t*4] = o4;
}

// ---------------- launch ------------------------------------------------------
extern "C" void kernel_launch(void* const* d_in, const int* in_sizes, int n_in,
                              void* d_out, int out_size)
{
    const float* x     = (const float*)d_in[0];
    const float* W_in  = (const float*)d_in[1];
    const float* b_in  = (const float*)d_in[2];
    const float* B_mat = (const float*)d_in[3];
    const float* C_mat = (const float*)d_in[4];
    const float* W_B   = (const float*)d_in[5];
    const float* b_B   = (const float*)d_in[6];
    const float* W_D   = (const float*)d_in[7];
    const float* b_D   = (const float*)d_in[8];
    const float* W_out = (const float*)d_in[9];
    const float* b_out = (const float*)d_in[10];
    const float* W_ig  = (const float*)d_in[11];
    const float* b_ig  = (const float*)d_in[12];
    const float* W_fg  = (const float*)d_in[13];
    const float* b_fg  = (const float*)d_in[14];
    const float* gamma = (const float*)d_in[15];
    const float* beta  = (const float*)d_in[16];
    float* out = (float*)d_out;

    void *p_xp, *p_z, *p_hs;
    void *p_xhi, *p_xlo, *p_xphi, *p_xplo, *p_y1hi, *p_y1lo;
    void *p_w0hi, *p_w0lo, *p_w1hi, *p_w1lo, *p_w2hi, *p_w2lo;
    cudaGetSymbolAddress(&p_xp, g_xp);
    cudaGetSymbolAddress(&p_z,  g_z);
    cudaGetSymbolAddress(&p_hs, g_hs);
    cudaGetSymbolAddress(&p_xhi,  g_xhi);  cudaGetSymbolAddress(&p_xlo,  g_xlo);
    cudaGetSymbolAddress(&p_xphi, g_xphi); cudaGetSymbolAddress(&p_xplo, g_xplo);
    cudaGetSymbolAddress(&p_y1hi, g_y1hi); cudaGetSymbolAddress(&p_y1lo, g_y1lo);
    cudaGetSymbolAddress(&p_w0hi, g_w0hi); cudaGetSymbolAddress(&p_w0lo, g_w0lo);
    cudaGetSymbolAddress(&p_w1hi, g_w1hi); cudaGetSymbolAddress(&p_w1lo, g_w1lo);
    cudaGetSymbolAddress(&p_w2hi, g_w2hi); cudaGetSymbolAddress(&p_w2lo, g_w2lo);

    static bool attr_done = false;
    if (!attr_done) {
        cudaFuncSetAttribute(bgemm_kernel<0>, cudaFuncAttributeMaxDynamicSharedMemorySize, SMEM_BYTES);
        cudaFuncSetAttribute(bgemm_kernel<1>, cudaFuncAttributeMaxDynamicSharedMemorySize, SMEM_BYTES);
        cudaFuncSetAttribute(bgemm_kernel<2>, cudaFuncAttributeMaxDynamicSharedMemorySize, SMEM_BYTES);
        attr_done = true;
    }

    prep_kernel<<<64, 256>>>(W_B, b_B, B_mat, W_ig, b_ig, W_fg, b_fg);

    // split inputs into bf16 hi/lo
    split_kernel<<<(MM*HH/2)/256, 256>>>(x, (uint32_t*)p_xhi, (uint32_t*)p_xlo, MM*HH/2);
    split_kernel<<<(HH*HH/2)/256, 256>>>(W_in,  (uint32_t*)p_w0hi, (uint32_t*)p_w0lo, HH*HH/2);
    split_kernel<<<(HH*HH/2)/256, 256>>>(W_D,   (uint32_t*)p_w1hi, (uint32_t*)p_w1lo, HH*HH/2);
    split_kernel<<<(HH*HH/2)/256, 256>>>(W_out, (uint32_t*)p_w2hi, (uint32_t*)p_w2lo, HH*HH/2);

    dim3 gg(HH/128, MM/128);   // (8, 256)

    // xp = x @ W_in + b_in   (fp32 + hi/lo)
    bgemm_kernel<0><<<gg, 256, SMEM_BYTES>>>(
        (const uint16_t*)p_xhi, (const uint16_t*)p_xlo,
        (const uint16_t*)p_w0hi, (const uint16_t*)p_w0lo,
        b_in, (float*)p_xp, (uint32_t*)p_xphi, (uint32_t*)p_xplo,
        nullptr, nullptr, nullptr, MM, HH, HH);

    // Bx / ig / fg (fused 48-wide projection)
    proj48_kernel<<<MM/256, 256>>>((const float*)p_xp);

    // h_t = fg*h + ig*Bx
    scan_kernel<<<1, 128>>>();

    // y1 = tanh(xp @ W_D + b_D + hs @ C_mat)   (hi/lo only)
    bgemm_kernel<1><<<gg, 256, SMEM_BYTES>>>(
        (const uint16_t*)p_xphi, (const uint16_t*)p_xplo,
        (const uint16_t*)p_w1hi, (const uint16_t*)p_w1lo,
        b_D, nullptr, (uint32_t*)p_y1hi, (uint32_t*)p_y1lo,
        (const float*)p_hs, C_mat, nullptr, MM, HH, HH);

    // z = y1 @ W_out + b_out + xp
    bgemm_kernel<2><<<gg, 256, SMEM_BYTES>>>(
        (const uint16_t*)p_y1hi, (const uint16_t*)p_y1lo,
        (const uint16_t*)p_w2hi, (const uint16_t*)p_w2lo,
        b_out, (float*)p_z, nullptr, nullptr,
        nullptr, nullptr, (const float*)p_xp, MM, HH, HH);

    // out = LayerNorm(z)
    ln_kernel<<<MM, 256>>>(gamma, beta, out);
}